// round 10
// baseline (speedup 1.0000x reference)
#include <cuda_runtime.h>

// ContrastiveTreeLoss, single-launch, delta formulation, v5.
//
// Shapes (fixed by the problem instance):
//   arc_scores [B=512, N=256, N=256] f32
//   gold_heads [B, N] i32
//   mask       [B, N] i32
//   neg_heads  [K=4, B, N] i32
//   out        scalar f32 = mean_{k,b} relu(MARGIN - gold_total[b] + neg_total[k,b])
//
// Delta identity (kept from v3): each negative differs from gold at <=2
// dependents, so
//   margin - gold + neg_k = margin + sum_{d: nh!=gh} mask[d]*(arc[b,nh,d]-arc[b,gh,d])
// eliminating the 130K-point random gather entirely (~3MB coalesced index
// streams + ~8K scattered loads chip-wide remain).
//
// v5: occupancy fix. v4 ran 64 fat CTAs -> only 64/148 SMs active (occ 12%).
// Now 128 CTAs x 4 warps, one warp per sentence: ~128 SMs active, gather
// phase latency roughly halves. Tail: 128-arrival last-CTA-done reduction.

#define TL_B 512
#define TL_N 256
#define TL_K 4
#define TL_MARGIN 2.0f
#define TL_WARPS 4                    // warps (sentences) per CTA
#define TL_GRID (TL_B / TL_WARPS)     // 128 CTAs

__device__ float g_partial[TL_GRID];
__device__ unsigned int g_done_count;   // zero-init; reset each launch by last CTA

__global__ __launch_bounds__(TL_WARPS * 32, 8)
void tree_loss_v5_kernel(const float* __restrict__ arc,
                         const int*   __restrict__ gold,
                         const int*   __restrict__ mask,
                         const int*   __restrict__ neg,
                         float*       __restrict__ out)
{
    const int lane = threadIdx.x & 31;
    const int warp = threadIdx.x >> 5;
    const int b    = blockIdx.x * TL_WARPS + warp;       // sentence for this warp

    const float* __restrict__ arcb  = arc + (size_t)b * TL_N * TL_N;
    const int4*  __restrict__ gold4 = (const int4*)(gold + b * TL_N);
    const int4*  __restrict__ mask4 = (const int4*)(mask + b * TL_N);

    float dk[TL_K] = {0.0f, 0.0f, 0.0f, 0.0f};          // delta_k partials

#pragma unroll
    for (int i = 0; i < TL_N / (32 * 4); i++) {          // 2 iterations
        const int idx = i * 32 + lane;                   // int4 index in the row
        const int d0  = idx * 4;                         // first dependent of this int4
        const int4 g4 = __ldg(gold4 + idx);
        const int4 m4 = __ldg(mask4 + idx);
        const int   gh[4] = {g4.x, g4.y, g4.z, g4.w};
        const float mm[4] = {(float)m4.x, (float)m4.y, (float)m4.z, (float)m4.w};

#pragma unroll
        for (int k = 0; k < TL_K; k++) {
            const int4* __restrict__ neg4 =
                (const int4*)(neg + ((size_t)k * TL_B + b) * TL_N);
            const int4 n4 = __ldg(neg4 + idx);
            const int nh[4] = {n4.x, n4.y, n4.z, n4.w};
#pragma unroll
            for (int j = 0; j < 4; j++) {
                const int d = d0 + j;
                if (d >= 1) {                            // dependent 0 excluded
                    int g = min(max(gh[j], 0), TL_N - 1);
                    int n = min(max(nh[j], 0), TL_N - 1);
                    if (n != g) {
                        // Rare path: <=2 lanes per (k, sentence). Two scattered
                        // loads, predicated off everywhere else.
                        dk[k] += (__ldg(arcb + n * TL_N + d) -
                                  __ldg(arcb + g * TL_N + d)) * mm[j];
                    }
                }
            }
        }
    }

    // Warp-reduce the 4 deltas; lane 0 forms the per-sentence loss.
#pragma unroll
    for (int k = 0; k < TL_K; k++) {
#pragma unroll
        for (int off = 16; off > 0; off >>= 1)
            dk[k] += __shfl_down_sync(0xffffffffu, dk[k], off);
    }

    __shared__ float wloss[TL_WARPS];
    if (lane == 0) {
        float loss = 0.0f;
#pragma unroll
        for (int k = 0; k < TL_K; k++)
            loss += fmaxf(TL_MARGIN + dk[k], 0.0f);
        wloss[warp] = loss;
    }
    __syncthreads();

    __shared__ bool is_last;
    if (threadIdx.x == 0) {
        float s = 0.0f;
#pragma unroll
        for (int w = 0; w < TL_WARPS; w++) s += wloss[w];
        g_partial[blockIdx.x] = s;
        __threadfence();                                 // release before the arrival
        unsigned int prev = atomicAdd(&g_done_count, 1u);
        is_last = (prev == (unsigned int)(TL_GRID - 1));
    }
    __syncthreads();

    if (is_last) {
        if (threadIdx.x == 0) __threadfence();           // acquire all writers
        __syncthreads();
        // Reduce 128 partials with the CTA's 128 threads (4 warps).
        float v = g_partial[threadIdx.x];
        __shared__ float rsh[TL_WARPS];
#pragma unroll
        for (int off = 16; off > 0; off >>= 1)
            v += __shfl_down_sync(0xffffffffu, v, off);
        if (lane == 0) rsh[warp] = v;
        __syncthreads();
        if (threadIdx.x == 0) {
            float s = 0.0f;
#pragma unroll
            for (int w = 0; w < TL_WARPS; w++) s += rsh[w];
            out[0] = s * (1.0f / (float)(TL_K * TL_B));
            atomicExch(&g_done_count, 0u);               // reset for next replay
        }
    }
}

extern "C" void kernel_launch(void* const* d_in, const int* in_sizes, int n_in,
                              void* d_out, int out_size)
{
    const float* arc  = (const float*)d_in[0];  // arc_scores [B,N,N]
    const int*   gold = (const int*)  d_in[1];  // gold_heads [B,N]
    const int*   mask = (const int*)  d_in[2];  // mask       [B,N]
    const int*   neg  = (const int*)  d_in[3];  // neg_heads  [K,B,N]
    (void)in_sizes; (void)n_in; (void)out_size;

    tree_loss_v5_kernel<<<TL_GRID, TL_WARPS * 32>>>(arc, gold, mask, neg, (float*)d_out);
}